// round 2
// baseline (speedup 1.0000x reference)
#include <cuda_runtime.h>
#include <math.h>

// Problem constants
#define BB 2
#define TT 2048
#define CC 1024
#define NH 16
#define HD 64
#define MROWS (BB*TT)      // 4096
#define QKVN  (3*CC)       // 3072

// Scratch (allocation-free rule: __device__ globals)
__device__ float g_qkv[MROWS * QKVN];   // [4096, 3072]
__device__ float g_y[MROWS * CC];       // [4096, 1024]

// ---------------------------------------------------------------------------
// Tiled FP32 GEMM with bias: out[M,N] = A[M,K] @ W[K,N] + bias[N]
// BM=BN=128, BK=16, 256 threads, 8x8 per-thread tile. (unchanged from R0)
// ---------------------------------------------------------------------------
__global__ void __launch_bounds__(256) sgemm_bias_kernel(
    const float* __restrict__ A, const float* __restrict__ W,
    const float* __restrict__ bias, float* __restrict__ out,
    int M, int N, int K)
{
    constexpr int BM = 128, BN = 128, BK = 16;
    __shared__ float As[BK][BM + 4];
    __shared__ float Bs[BK][BN + 4];

    const int tid = threadIdx.x;
    const int tx = tid & 15;    // n direction
    const int ty = tid >> 4;    // m direction
    const int m0 = blockIdx.y * BM;
    const int n0 = blockIdx.x * BN;

    float acc[8][8];
#pragma unroll
    for (int i = 0; i < 8; i++)
#pragma unroll
        for (int j = 0; j < 8; j++) acc[i][j] = 0.0f;

    const int ar0 = tid >> 2;
    const int ac0 = tid & 3;

    for (int k0 = 0; k0 < K; k0 += BK) {
#pragma unroll
        for (int i = 0; i < 2; i++) {
            int row = ar0 + i * 64;
            float4 v = *(const float4*)&A[(size_t)(m0 + row) * K + k0 + ac0 * 4];
            As[ac0 * 4 + 0][row] = v.x;
            As[ac0 * 4 + 1][row] = v.y;
            As[ac0 * 4 + 2][row] = v.z;
            As[ac0 * 4 + 3][row] = v.w;
        }
#pragma unroll
        for (int i = 0; i < 2; i++) {
            int p = tid + i * 256;
            int row = p >> 5, c4 = p & 31;
            *(float4*)&Bs[row][c4 * 4] =
                *(const float4*)&W[(size_t)(k0 + row) * N + n0 + c4 * 4];
        }
        __syncthreads();

#pragma unroll
        for (int k = 0; k < BK; k++) {
            float a[8], b[8];
#pragma unroll
            for (int i = 0; i < 8; i++) a[i] = As[k][ty * 8 + i];
#pragma unroll
            for (int j = 0; j < 8; j++) b[j] = Bs[k][tx * 8 + j];
#pragma unroll
            for (int i = 0; i < 8; i++)
#pragma unroll
                for (int j = 0; j < 8; j++)
                    acc[i][j] += a[i] * b[j];
        }
        __syncthreads();
    }

#pragma unroll
    for (int i = 0; i < 8; i++) {
        int r = m0 + ty * 8 + i;
#pragma unroll
        for (int j = 0; j < 8; j += 4) {
            int cn = n0 + tx * 8 + j;
            float4 v;
            v.x = acc[i][j + 0] + bias[cn + 0];
            v.y = acc[i][j + 1] + bias[cn + 1];
            v.z = acc[i][j + 2] + bias[cn + 2];
            v.w = acc[i][j + 3] + bias[cn + 3];
            *(float4*)&out[(size_t)r * N + cn] = v;
        }
    }
}

// ---------------------------------------------------------------------------
// Causal flash attention, fp32 — split-D version.
// Grid: (T/128, B*NH). Block: 256 threads; each PAIR of threads owns one
// query: thread (2q) handles d[0:32), thread (2q+1) handles d[32:64).
// Per-thread register state: q-half (8 float4) + acc-half (8 float4) ≈ 64
// regs + temps → ~2 CTAs/SM (16 warps) vs 4 warps before.
// QK dot: each thread computes a half-dot, combined with one shfl_xor(1).
// Both pair members redundantly compute the softmax scalars (deterministic,
// identical), so no further communication is needed.
// ---------------------------------------------------------------------------
__global__ void __launch_bounds__(256) flash_attn_kernel(
    const float* __restrict__ qkv, float* __restrict__ y)
{
    const int qblk = blockIdx.x;           // 0..15
    const int bh   = blockIdx.y;           // 0..31
    const int b    = bh >> 4;
    const int h    = bh & 15;
    const int tid  = threadIdx.x;
    const int qi   = tid >> 1;             // 0..127 query within block
    const int half = tid & 1;              // which half of D
    const int q    = qblk * 128 + qi;      // global query index
    const float scale = 0.125f;            // 1/sqrt(64)

    __shared__ float4 ks[64][16];
    __shared__ float4 vs[64][16];

    // Load this thread's half of the query row (32 floats = 8 float4)
    float4 qv[8];
    const float* qrow = qkv + (size_t)(b * TT + q) * QKVN + h * HD + half * 32;
#pragma unroll
    for (int i = 0; i < 8; i++) qv[i] = *(const float4*)(qrow + i * 4);

    float4 acc[8];
#pragma unroll
    for (int i = 0; i < 8; i++) acc[i] = make_float4(0.f, 0.f, 0.f, 0.f);
    float m = -INFINITY, l = 0.0f;

    const int cbase = half * 8;            // float4 column offset in smem tiles
    const int kend = qblk * 128 + 128;     // exclusive key bound for this block

    for (int kt = 0; kt < kend; kt += 64) {
        // Cooperative load of 64 keys + 64 values (each thread: 4 float4 per tensor)
        for (int p = tid; p < 1024; p += 256) {
            int r = p >> 4, c = p & 15;
            const float* krow = qkv + (size_t)(b * TT + kt + r) * QKVN + CC + h * HD;
            ks[r][c] = *(const float4*)(krow + c * 4);
            vs[r][c] = *(const float4*)(krow + CC + c * 4);
        }
        __syncthreads();

#pragma unroll 1
        for (int c0 = 0; c0 < 64; c0 += 8) {
            float s[8];
            float cmax = -INFINITY;
#pragma unroll
            for (int jj = 0; jj < 8; jj++) {
                int j = c0 + jj;
                float dot = 0.0f;
#pragma unroll
                for (int i = 0; i < 8; i++) {
                    float4 kv = ks[j][cbase + i];
                    dot += qv[i].x * kv.x + qv[i].y * kv.y +
                           qv[i].z * kv.z + qv[i].w * kv.w;
                }
                // combine half-dots across the pair (lanes 2q, 2q+1)
                dot += __shfl_xor_sync(0xffffffffu, dot, 1);
                s[jj] = (kt + j <= q) ? dot * scale : -INFINITY;
                cmax = fmaxf(cmax, s[jj]);
            }
            if (cmax > -INFINITY) {
                float m_new = fmaxf(m, cmax);
                float corr  = __expf(m - m_new);   // m==-inf -> 0
                l *= corr;
#pragma unroll
                for (int i = 0; i < 8; i++) {
                    acc[i].x *= corr; acc[i].y *= corr;
                    acc[i].z *= corr; acc[i].w *= corr;
                }
#pragma unroll
                for (int jj = 0; jj < 8; jj++) {
                    float p = __expf(s[jj] - m_new);
                    l += p;
                    int j = c0 + jj;
#pragma unroll
                    for (int i = 0; i < 8; i++) {
                        float4 vv = vs[j][cbase + i];
                        acc[i].x += p * vv.x; acc[i].y += p * vv.y;
                        acc[i].z += p * vv.z; acc[i].w += p * vv.w;
                    }
                }
                m = m_new;
            }
        }
        __syncthreads();
    }

    const float inv = 1.0f / l;
    float* yrow = y + (size_t)(b * TT + q) * CC + h * HD + half * 32;
#pragma unroll
    for (int i = 0; i < 8; i++) {
        float4 v;
        v.x = acc[i].x * inv; v.y = acc[i].y * inv;
        v.z = acc[i].z * inv; v.w = acc[i].w * inv;
        *(float4*)(yrow + i * 4) = v;
    }
}

// ---------------------------------------------------------------------------
// Launch
// ---------------------------------------------------------------------------
extern "C" void kernel_launch(void* const* d_in, const int* in_sizes, int n_in,
                              void* d_out, int out_size)
{
    const float* x     = (const float*)d_in[0];   // [2,2048,1024]
    const float* w_qkv = (const float*)d_in[1];   // [1024,3072]
    const float* b_qkv = (const float*)d_in[2];   // [3072]
    const float* w_out = (const float*)d_in[3];   // [1024,1024]
    const float* b_out = (const float*)d_in[4];   // [1024]
    float* out = (float*)d_out;                   // [2,2048,1024]

    float *qkv, *y;
    cudaGetSymbolAddress((void**)&qkv, g_qkv);
    cudaGetSymbolAddress((void**)&y, g_y);

    // 1) QKV projection: [4096,1024] @ [1024,3072] + b_qkv
    sgemm_bias_kernel<<<dim3(QKVN / 128, MROWS / 128), 256>>>(
        x, w_qkv, b_qkv, qkv, MROWS, QKVN, CC);

    // 2) Causal multi-head attention -> y [4096,1024] in (b,t,h,d) layout
    flash_attn_kernel<<<dim3(TT / 128, BB * NH), 256>>>(qkv, y);

    // 3) Output projection: [4096,1024] @ [1024,1024] + b_out
    sgemm_bias_kernel<<<dim3(CC / 128, MROWS / 128), 256>>>(
        y, w_out, b_out, out, MROWS, CC, CC);
}

// round 3
// speedup vs baseline: 1.4301x; 1.4301x over previous
#include <cuda_runtime.h>
#include <math.h>
#include <stdint.h>

// Problem constants
#define BB 2
#define TT 2048
#define CC 1024
#define NH 16
#define HD 64
#define MROWS (BB*TT)      // 4096
#define QKVN  (3*CC)       // 3072

// Scratch (allocation-free rule: __device__ globals)
__device__ float g_qkv[MROWS * QKVN];   // [4096, 3072]
__device__ float g_y[MROWS * CC];       // [4096, 1024]

// ---------------------------------------------------------------------------
// tf32 helpers
// ---------------------------------------------------------------------------
__device__ __forceinline__ uint32_t f2tf32(float f) {
    uint32_t u;
    asm("cvt.rna.tf32.f32 %0, %1;" : "=r"(u) : "f"(f));
    return u;
}

__device__ __forceinline__ void mma_tf32(
    float& c0, float& c1, float& c2, float& c3,
    uint32_t a0, uint32_t a1, uint32_t a2, uint32_t a3,
    uint32_t b0, uint32_t b1)
{
    asm volatile(
        "mma.sync.aligned.m16n8k8.row.col.f32.tf32.tf32.f32 "
        "{%0,%1,%2,%3}, {%4,%5,%6,%7}, {%8,%9}, {%0,%1,%2,%3};"
        : "+f"(c0), "+f"(c1), "+f"(c2), "+f"(c3)
        : "r"(a0), "r"(a1), "r"(a2), "r"(a3), "r"(b0), "r"(b1));
}

// ---------------------------------------------------------------------------
// tf32 tensor-core GEMM with bias: out[M,N] = A[M,K] @ W[K,N] + bias[N]
// BM=BN=128, BK=16, 256 threads = 8 warps in 2(m) x 4(n); each warp owns a
// 64x32 tile computed as 4x4 m16n8k8 MMAs per 8-wide k-chunk.
// Requires M%128==0, N%128==0, K%16==0.
// ---------------------------------------------------------------------------
__global__ void __launch_bounds__(256) gemm_tf32_bias(
    const float* __restrict__ A, const float* __restrict__ W,
    const float* __restrict__ bias, float* __restrict__ out,
    int M, int N, int K)
{
    constexpr int BM = 128, BN = 128, BK = 16;
    constexpr int APAD = 4;   // As row stride 20 -> conflict-free frag reads
    constexpr int BPAD = 8;   // Bs row stride 136 -> conflict-free frag reads
    __shared__ float As[BM][BK + APAD];
    __shared__ float Bs[BK][BN + BPAD];

    const int tid  = threadIdx.x;
    const int warp = tid >> 5;
    const int lane = tid & 31;
    const int g    = lane >> 2;       // groupID (row within 8)
    const int tg   = lane & 3;        // threadID_in_group

    const int wm = (warp & 1) * 64;   // warp m offset
    const int wn = (warp >> 1) * 32;  // warp n offset

    const int m0 = blockIdx.y * BM;
    const int n0 = blockIdx.x * BN;

    float acc[4][4][4];               // [mtile][ntile][c0..c3]
#pragma unroll
    for (int i = 0; i < 4; i++)
#pragma unroll
        for (int j = 0; j < 4; j++)
#pragma unroll
            for (int r = 0; r < 4; r++) acc[i][j][r] = 0.0f;

    // Global-load mapping (per thread: 2 float4 of A, 2 float4 of B per tile)
    const int ar  = tid >> 2;         // A row 0..63 (+64 second)
    const int ac4 = tid & 3;          // A float4-col within BK
    const int br  = tid >> 5;         // B row 0..7 (+8 second)
    const int bc4 = tid & 31;         // B float4-col within BN

    const int niter = K / BK;

    // Preload tile 0
    float4 a_reg[2], b_reg[2];
#pragma unroll
    for (int i = 0; i < 2; i++) {
        a_reg[i] = *(const float4*)&A[(size_t)(m0 + ar + i * 64) * K + ac4 * 4];
        b_reg[i] = *(const float4*)&W[(size_t)(br + i * 8) * N + n0 + bc4 * 4];
    }

    for (int it = 0; it < niter; it++) {
        // Stage current tile into smem
#pragma unroll
        for (int i = 0; i < 2; i++) {
            *(float4*)&As[ar + i * 64][ac4 * 4] = a_reg[i];
            *(float4*)&Bs[br + i * 8][bc4 * 4]  = b_reg[i];
        }
        __syncthreads();

        // Prefetch next tile
        if (it + 1 < niter) {
            int k0 = (it + 1) * BK;
#pragma unroll
            for (int i = 0; i < 2; i++) {
                a_reg[i] = *(const float4*)&A[(size_t)(m0 + ar + i * 64) * K + k0 + ac4 * 4];
                b_reg[i] = *(const float4*)&W[(size_t)(k0 + br + i * 8) * N + n0 + bc4 * 4];
            }
        }

        // Two k8 chunks
#pragma unroll
        for (int kk = 0; kk < BK; kk += 8) {
            uint32_t af[4][4];
#pragma unroll
            for (int mt = 0; mt < 4; mt++) {
                int r0 = wm + mt * 16 + g;
                af[mt][0] = f2tf32(As[r0    ][kk + tg    ]);
                af[mt][1] = f2tf32(As[r0 + 8][kk + tg    ]);
                af[mt][2] = f2tf32(As[r0    ][kk + tg + 4]);
                af[mt][3] = f2tf32(As[r0 + 8][kk + tg + 4]);
            }
            uint32_t bf[4][2];
#pragma unroll
            for (int nt = 0; nt < 4; nt++) {
                int c0 = wn + nt * 8 + g;
                bf[nt][0] = f2tf32(Bs[kk + tg    ][c0]);
                bf[nt][1] = f2tf32(Bs[kk + tg + 4][c0]);
            }
#pragma unroll
            for (int mt = 0; mt < 4; mt++)
#pragma unroll
                for (int nt = 0; nt < 4; nt++)
                    mma_tf32(acc[mt][nt][0], acc[mt][nt][1],
                             acc[mt][nt][2], acc[mt][nt][3],
                             af[mt][0], af[mt][1], af[mt][2], af[mt][3],
                             bf[nt][0], bf[nt][1]);
        }
        __syncthreads();
    }

    // Epilogue: c0,c1 -> (row, 2tg..2tg+1); c2,c3 -> (row+8, same cols)
#pragma unroll
    for (int mt = 0; mt < 4; mt++) {
        int row = m0 + wm + mt * 16 + g;
#pragma unroll
        for (int nt = 0; nt < 4; nt++) {
            int col = n0 + wn + nt * 8 + tg * 2;
            float2 bv = *(const float2*)&bias[col];
            float2 v0, v1;
            v0.x = acc[mt][nt][0] + bv.x;
            v0.y = acc[mt][nt][1] + bv.y;
            v1.x = acc[mt][nt][2] + bv.x;
            v1.y = acc[mt][nt][3] + bv.y;
            *(float2*)&out[(size_t)row * N + col]       = v0;
            *(float2*)&out[(size_t)(row + 8) * N + col] = v1;
        }
    }
}

// ---------------------------------------------------------------------------
// Causal flash attention, fp32 (R0 version: 128 threads, 1 query/thread).
// ---------------------------------------------------------------------------
__global__ void __launch_bounds__(128) flash_attn_kernel(
    const float* __restrict__ qkv, float* __restrict__ y)
{
    const int qblk = blockIdx.x;          // 0..15
    const int bh   = blockIdx.y;          // 0..31
    const int b    = bh >> 4;
    const int h    = bh & 15;
    const int tid  = threadIdx.x;
    const int q    = qblk * 128 + tid;
    const float scale = 0.125f;           // 1/sqrt(64)

    __shared__ float4 ks[64][16];
    __shared__ float4 vs[64][16];

    float4 qv[16];
    const float* qrow = qkv + (size_t)(b * TT + q) * QKVN + h * HD;
#pragma unroll
    for (int i = 0; i < 16; i++) qv[i] = *(const float4*)(qrow + i * 4);

    float4 acc[16];
#pragma unroll
    for (int i = 0; i < 16; i++) acc[i] = make_float4(0.f, 0.f, 0.f, 0.f);
    float m = -INFINITY, l = 0.0f;

    const int kend = qblk * 128 + 128;
    for (int kt = 0; kt < kend; kt += 64) {
        for (int p = tid; p < 1024; p += 128) {
            int r = p >> 4, c = p & 15;
            const float* krow = qkv + (size_t)(b * TT + kt + r) * QKVN + CC + h * HD;
            ks[r][c] = *(const float4*)(krow + c * 4);
            vs[r][c] = *(const float4*)(krow + CC + c * 4);
        }
        __syncthreads();

#pragma unroll 1
        for (int c0 = 0; c0 < 64; c0 += 8) {
            float s[8];
            float cmax = -INFINITY;
#pragma unroll
            for (int jj = 0; jj < 8; jj++) {
                int j = c0 + jj;
                float dot = 0.0f;
#pragma unroll
                for (int i = 0; i < 16; i++) {
                    float4 kv = ks[j][i];
                    dot += qv[i].x * kv.x + qv[i].y * kv.y +
                           qv[i].z * kv.z + qv[i].w * kv.w;
                }
                s[jj] = (kt + j <= q) ? dot * scale : -INFINITY;
                cmax = fmaxf(cmax, s[jj]);
            }
            if (cmax > -INFINITY) {
                float m_new = fmaxf(m, cmax);
                float corr  = __expf(m - m_new);
                l *= corr;
#pragma unroll
                for (int i = 0; i < 16; i++) {
                    acc[i].x *= corr; acc[i].y *= corr;
                    acc[i].z *= corr; acc[i].w *= corr;
                }
#pragma unroll
                for (int jj = 0; jj < 8; jj++) {
                    float p = __expf(s[jj] - m_new);
                    l += p;
                    int j = c0 + jj;
#pragma unroll
                    for (int i = 0; i < 16; i++) {
                        float4 vv = vs[j][i];
                        acc[i].x += p * vv.x; acc[i].y += p * vv.y;
                        acc[i].z += p * vv.z; acc[i].w += p * vv.w;
                    }
                }
                m = m_new;
            }
        }
        __syncthreads();
    }

    const float inv = 1.0f / l;
    float* yrow = y + (size_t)(b * TT + q) * CC + h * HD;
#pragma unroll
    for (int i = 0; i < 16; i++) {
        float4 v;
        v.x = acc[i].x * inv; v.y = acc[i].y * inv;
        v.z = acc[i].z * inv; v.w = acc[i].w * inv;
        *(float4*)(yrow + i * 4) = v;
    }
}

// ---------------------------------------------------------------------------
// Launch
// ---------------------------------------------------------------------------
extern "C" void kernel_launch(void* const* d_in, const int* in_sizes, int n_in,
                              void* d_out, int out_size)
{
    const float* x     = (const float*)d_in[0];   // [2,2048,1024]
    const float* w_qkv = (const float*)d_in[1];   // [1024,3072]
    const float* b_qkv = (const float*)d_in[2];   // [3072]
    const float* w_out = (const float*)d_in[3];   // [1024,1024]
    const float* b_out = (const float*)d_in[4];   // [1024]
    float* out = (float*)d_out;                   // [2,2048,1024]

    float *qkv, *y;
    cudaGetSymbolAddress((void**)&qkv, g_qkv);
    cudaGetSymbolAddress((void**)&y, g_y);

    // 1) QKV projection: [4096,1024] @ [1024,3072] + b_qkv   (tf32 tensor cores)
    gemm_tf32_bias<<<dim3(QKVN / 128, MROWS / 128), 256>>>(
        x, w_qkv, b_qkv, qkv, MROWS, QKVN, CC);

    // 2) Causal multi-head attention -> y [4096,1024] in (b,t,h,d) layout
    flash_attn_kernel<<<dim3(TT / 128, BB * NH), 128>>>(qkv, y);

    // 3) Output projection: [4096,1024] @ [1024,1024] + b_out (tf32 tensor cores)
    gemm_tf32_bias<<<dim3(CC / 128, MROWS / 128), 256>>>(
        y, w_out, b_out, out, MROWS, CC, CC);
}

// round 4
// speedup vs baseline: 5.2425x; 3.6658x over previous
#include <cuda_runtime.h>
#include <cuda_fp16.h>
#include <math.h>
#include <stdint.h>

// Problem constants
#define BB 2
#define TT 2048
#define CC 1024
#define NH 16
#define HD 64
#define MROWS (BB*TT)      // 4096
#define QKVN  (3*CC)       // 3072

// Scratch (allocation-free rule: __device__ globals)
__device__ float g_qkv[MROWS * QKVN];   // [4096, 3072]
__device__ float g_y[MROWS * CC];       // [4096, 1024]

// ---------------------------------------------------------------------------
// tf32 helpers
// ---------------------------------------------------------------------------
__device__ __forceinline__ uint32_t f2tf32(float f) {
    uint32_t u;
    asm("cvt.rna.tf32.f32 %0, %1;" : "=r"(u) : "f"(f));
    return u;
}

__device__ __forceinline__ void mma_tf32(
    float& c0, float& c1, float& c2, float& c3,
    uint32_t a0, uint32_t a1, uint32_t a2, uint32_t a3,
    uint32_t b0, uint32_t b1)
{
    asm volatile(
        "mma.sync.aligned.m16n8k8.row.col.f32.tf32.tf32.f32 "
        "{%0,%1,%2,%3}, {%4,%5,%6,%7}, {%8,%9}, {%0,%1,%2,%3};"
        : "+f"(c0), "+f"(c1), "+f"(c2), "+f"(c3)
        : "r"(a0), "r"(a1), "r"(a2), "r"(a3), "r"(b0), "r"(b1));
}

__device__ __forceinline__ void mma_f16(
    float& c0, float& c1, float& c2, float& c3,
    uint32_t a0, uint32_t a1, uint32_t a2, uint32_t a3,
    uint32_t b0, uint32_t b1)
{
    asm volatile(
        "mma.sync.aligned.m16n8k16.row.col.f32.f16.f16.f32 "
        "{%0,%1,%2,%3}, {%4,%5,%6,%7}, {%8,%9}, {%0,%1,%2,%3};"
        : "+f"(c0), "+f"(c1), "+f"(c2), "+f"(c3)
        : "r"(a0), "r"(a1), "r"(a2), "r"(a3), "r"(b0), "r"(b1));
}

__device__ __forceinline__ void ldsm_x4_trans(
    uint32_t& r0, uint32_t& r1, uint32_t& r2, uint32_t& r3, uint32_t addr)
{
    asm volatile(
        "ldmatrix.sync.aligned.m8n8.x4.trans.shared.b16 {%0,%1,%2,%3}, [%4];"
        : "=r"(r0), "=r"(r1), "=r"(r2), "=r"(r3) : "r"(addr));
}

// ---------------------------------------------------------------------------
// tf32 tensor-core GEMM with bias (unchanged from R2)
// ---------------------------------------------------------------------------
__global__ void __launch_bounds__(256) gemm_tf32_bias(
    const float* __restrict__ A, const float* __restrict__ W,
    const float* __restrict__ bias, float* __restrict__ out,
    int M, int N, int K)
{
    constexpr int BM = 128, BN = 128, BK = 16;
    constexpr int APAD = 4;
    constexpr int BPAD = 8;
    __shared__ float As[BM][BK + APAD];
    __shared__ float Bs[BK][BN + BPAD];

    const int tid  = threadIdx.x;
    const int warp = tid >> 5;
    const int lane = tid & 31;
    const int g    = lane >> 2;
    const int tg   = lane & 3;

    const int wm = (warp & 1) * 64;
    const int wn = (warp >> 1) * 32;

    const int m0 = blockIdx.y * BM;
    const int n0 = blockIdx.x * BN;

    float acc[4][4][4];
#pragma unroll
    for (int i = 0; i < 4; i++)
#pragma unroll
        for (int j = 0; j < 4; j++)
#pragma unroll
            for (int r = 0; r < 4; r++) acc[i][j][r] = 0.0f;

    const int ar  = tid >> 2;
    const int ac4 = tid & 3;
    const int br  = tid >> 5;
    const int bc4 = tid & 31;

    const int niter = K / BK;

    float4 a_reg[2], b_reg[2];
#pragma unroll
    for (int i = 0; i < 2; i++) {
        a_reg[i] = *(const float4*)&A[(size_t)(m0 + ar + i * 64) * K + ac4 * 4];
        b_reg[i] = *(const float4*)&W[(size_t)(br + i * 8) * N + n0 + bc4 * 4];
    }

    for (int it = 0; it < niter; it++) {
#pragma unroll
        for (int i = 0; i < 2; i++) {
            *(float4*)&As[ar + i * 64][ac4 * 4] = a_reg[i];
            *(float4*)&Bs[br + i * 8][bc4 * 4]  = b_reg[i];
        }
        __syncthreads();

        if (it + 1 < niter) {
            int k0 = (it + 1) * BK;
#pragma unroll
            for (int i = 0; i < 2; i++) {
                a_reg[i] = *(const float4*)&A[(size_t)(m0 + ar + i * 64) * K + k0 + ac4 * 4];
                b_reg[i] = *(const float4*)&W[(size_t)(k0 + br + i * 8) * N + n0 + bc4 * 4];
            }
        }

#pragma unroll
        for (int kk = 0; kk < BK; kk += 8) {
            uint32_t af[4][4];
#pragma unroll
            for (int mt = 0; mt < 4; mt++) {
                int r0 = wm + mt * 16 + g;
                af[mt][0] = f2tf32(As[r0    ][kk + tg    ]);
                af[mt][1] = f2tf32(As[r0 + 8][kk + tg    ]);
                af[mt][2] = f2tf32(As[r0    ][kk + tg + 4]);
                af[mt][3] = f2tf32(As[r0 + 8][kk + tg + 4]);
            }
            uint32_t bf[4][2];
#pragma unroll
            for (int nt = 0; nt < 4; nt++) {
                int c0 = wn + nt * 8 + g;
                bf[nt][0] = f2tf32(Bs[kk + tg    ][c0]);
                bf[nt][1] = f2tf32(Bs[kk + tg + 4][c0]);
            }
#pragma unroll
            for (int mt = 0; mt < 4; mt++)
#pragma unroll
                for (int nt = 0; nt < 4; nt++)
                    mma_tf32(acc[mt][nt][0], acc[mt][nt][1],
                             acc[mt][nt][2], acc[mt][nt][3],
                             af[mt][0], af[mt][1], af[mt][2], af[mt][3],
                             bf[nt][0], bf[nt][1]);
        }
        __syncthreads();
    }

#pragma unroll
    for (int mt = 0; mt < 4; mt++) {
        int row = m0 + wm + mt * 16 + g;
#pragma unroll
        for (int nt = 0; nt < 4; nt++) {
            int col = n0 + wn + nt * 8 + tg * 2;
            float2 bv = *(const float2*)&bias[col];
            float2 v0, v1;
            v0.x = acc[mt][nt][0] + bv.x;
            v0.y = acc[mt][nt][1] + bv.y;
            v1.x = acc[mt][nt][2] + bv.x;
            v1.y = acc[mt][nt][3] + bv.y;
            *(float2*)&out[(size_t)row * N + col]       = v0;
            *(float2*)&out[(size_t)(row + 8) * N + col] = v1;
        }
    }
}

// ---------------------------------------------------------------------------
// Tensor-core causal flash attention (FA2 style).
// Grid: (T/64, B*NH). Block: 128 threads = 4 warps; warp w owns query rows
// [w*16, w*16+16) of the 64-query CTA tile. D = 64.
//  - S = Q*K^T via tf32 m16n8k8 (Q frags in registers, scaled by 1/8).
//  - online softmax per row (f32), P kept in registers.
//  - P*V via f16 m16n8k16; P acc-layout == A-frag layout after half2 cvt;
//    V staged fp16 row-major in smem, B-frags via ldmatrix.x4.trans.
// ---------------------------------------------------------------------------
#define KPAD 4    // Ks row stride 68 floats
#define VPAD 8    // Vs row stride 72 halfs (144B, 16B-aligned rows)

__global__ void __launch_bounds__(128) flash_attn_mma(
    const float* __restrict__ qkv, float* __restrict__ y)
{
    const int qb  = blockIdx.x;            // 0..31 (64-query tile)
    const int bh  = blockIdx.y;            // 0..31
    const int b   = bh >> 4;
    const int h   = bh & 15;
    const int tid = threadIdx.x;
    const int w   = tid >> 5;
    const int lane = tid & 31;
    const int g   = lane >> 2;             // 0..7
    const int tg  = lane & 3;              // 0..3

    __shared__ __align__(16) float Ks[64][HD + KPAD];
    __shared__ __align__(16) __half Vs[64][HD + VPAD];

    const float* base = qkv + (size_t)(b * TT) * QKVN + h * HD;

    // ---- Stage Q tile through Ks, build scaled tf32 A-fragments ----
    {
        for (int p = tid; p < 64 * 16; p += 128) {
            int r = p >> 4, c4 = p & 15;
            *(float4*)&Ks[r][c4 * 4] =
                *(const float4*)&base[(size_t)(qb * 64 + r) * QKVN + c4 * 4];
        }
        __syncthreads();
    }

    uint32_t aq[8][4];                     // Q frags per k8-chunk
    const float qscale = 0.125f;           // 1/sqrt(64)
#pragma unroll
    for (int kc = 0; kc < 8; kc++) {
        int r0 = w * 16 + g;
        aq[kc][0] = f2tf32(Ks[r0    ][kc * 8 + tg    ] * qscale);
        aq[kc][1] = f2tf32(Ks[r0 + 8][kc * 8 + tg    ] * qscale);
        aq[kc][2] = f2tf32(Ks[r0    ][kc * 8 + tg + 4] * qscale);
        aq[kc][3] = f2tf32(Ks[r0 + 8][kc * 8 + tg + 4] * qscale);
    }
    __syncthreads();

    // ---- Online-softmax state ----
    float o[8][4];                          // O acc: 8 D-tiles of m16n8
#pragma unroll
    for (int nt = 0; nt < 8; nt++)
#pragma unroll
        for (int r = 0; r < 4; r++) o[nt][r] = 0.0f;
    float m0r = -INFINITY, m1r = -INFINITY; // row max (rows g, g+8)
    float l0 = 0.0f, l1 = 0.0f;             // row sum

    const int ntiles = qb + 1;              // causal: key tiles 0..qb

    for (int t = 0; t < ntiles; t++) {
        const int kt = t * 64;
        const bool diag = (t == ntiles - 1);

        // ---- Load K tile (f32) and V tile (fp16) ----
        for (int p = tid; p < 64 * 16; p += 128) {
            int r = p >> 4, c4 = p & 15;
            const float* krow = base + (size_t)(kt + r) * QKVN + CC;
            *(float4*)&Ks[r][c4 * 4] = *(const float4*)&krow[c4 * 4];
            float4 v = *(const float4*)&krow[CC + c4 * 4];
            *(half2*)&Vs[r][c4 * 4]     = __floats2half2_rn(v.x, v.y);
            *(half2*)&Vs[r][c4 * 4 + 2] = __floats2half2_rn(v.z, v.w);
        }
        __syncthreads();

        // ---- S = Q K^T : 8 n-tiles (keys), 8 k-chunks (dims) ----
        float s[8][4];
#pragma unroll
        for (int nt = 0; nt < 8; nt++)
#pragma unroll
            for (int r = 0; r < 4; r++) s[nt][r] = 0.0f;

#pragma unroll
        for (int kc = 0; kc < 8; kc++) {
            uint32_t bf[8][2];
#pragma unroll
            for (int nt = 0; nt < 8; nt++) {
                bf[nt][0] = f2tf32(Ks[nt * 8 + g][kc * 8 + tg    ]);
                bf[nt][1] = f2tf32(Ks[nt * 8 + g][kc * 8 + tg + 4]);
            }
#pragma unroll
            for (int nt = 0; nt < 8; nt++)
                mma_tf32(s[nt][0], s[nt][1], s[nt][2], s[nt][3],
                         aq[kc][0], aq[kc][1], aq[kc][2], aq[kc][3],
                         bf[nt][0], bf[nt][1]);
        }

        // ---- causal mask on the diagonal tile ----
        if (diag) {
            int row0 = w * 16 + g;          // local query rows
            int row1 = row0 + 8;
#pragma unroll
            for (int nt = 0; nt < 8; nt++) {
                int c0 = nt * 8 + tg * 2;   // local key cols
                if (c0     > row0) s[nt][0] = -INFINITY;
                if (c0 + 1 > row0) s[nt][1] = -INFINITY;
                if (c0     > row1) s[nt][2] = -INFINITY;
                if (c0 + 1 > row1) s[nt][3] = -INFINITY;
            }
        }

        // ---- row max ----
        float cm0 = -INFINITY, cm1 = -INFINITY;
#pragma unroll
        for (int nt = 0; nt < 8; nt++) {
            cm0 = fmaxf(cm0, fmaxf(s[nt][0], s[nt][1]));
            cm1 = fmaxf(cm1, fmaxf(s[nt][2], s[nt][3]));
        }
        cm0 = fmaxf(cm0, __shfl_xor_sync(0xffffffffu, cm0, 1));
        cm0 = fmaxf(cm0, __shfl_xor_sync(0xffffffffu, cm0, 2));
        cm1 = fmaxf(cm1, __shfl_xor_sync(0xffffffffu, cm1, 1));
        cm1 = fmaxf(cm1, __shfl_xor_sync(0xffffffffu, cm1, 2));

        float mn0 = fmaxf(m0r, cm0);
        float mn1 = fmaxf(m1r, cm1);
        float corr0 = __expf(m0r - mn0);
        float corr1 = __expf(m1r - mn1);
        m0r = mn0; m1r = mn1;

        // ---- P = exp(S - m), partial row sums, half2 A-frags ----
        uint32_t p01[8], p23[8];
        float ps0 = 0.0f, ps1 = 0.0f;
#pragma unroll
        for (int nt = 0; nt < 8; nt++) {
            float e0 = __expf(s[nt][0] - mn0);
            float e1 = __expf(s[nt][1] - mn0);
            float e2 = __expf(s[nt][2] - mn1);
            float e3 = __expf(s[nt][3] - mn1);
            ps0 += e0 + e1;
            ps1 += e2 + e3;
            half2 h01 = __floats2half2_rn(e0, e1);
            half2 h23 = __floats2half2_rn(e2, e3);
            p01[nt] = *(uint32_t*)&h01;
            p23[nt] = *(uint32_t*)&h23;
        }
        ps0 += __shfl_xor_sync(0xffffffffu, ps0, 1);
        ps0 += __shfl_xor_sync(0xffffffffu, ps0, 2);
        ps1 += __shfl_xor_sync(0xffffffffu, ps1, 1);
        ps1 += __shfl_xor_sync(0xffffffffu, ps1, 2);
        l0 = l0 * corr0 + ps0;
        l1 = l1 * corr1 + ps1;

        // ---- rescale O ----
#pragma unroll
        for (int nt = 0; nt < 8; nt++) {
            o[nt][0] *= corr0; o[nt][1] *= corr0;
            o[nt][2] *= corr1; o[nt][3] *= corr1;
        }

        // ---- O += P V : 4 k16-chunks (keys), 8 n-tiles (dims) ----
#pragma unroll
        for (int kc = 0; kc < 4; kc++) {
            uint32_t pa0 = p01[2 * kc],     pa1 = p23[2 * kc];
            uint32_t pa2 = p01[2 * kc + 1], pa3 = p23[2 * kc + 1];
#pragma unroll
            for (int np = 0; np < 4; np++) {   // n-tile pairs
                int sub = lane >> 3;           // 0..3
                int key = kc * 16 + (lane & 7) + (sub & 1) * 8;
                int dim = np * 16 + (sub >> 1) * 8;
                uint32_t addr = (uint32_t)__cvta_generic_to_shared(&Vs[key][dim]);
                uint32_t b0, b1, b2, b3;
                ldsm_x4_trans(b0, b1, b2, b3, addr);
                mma_f16(o[2*np][0], o[2*np][1], o[2*np][2], o[2*np][3],
                        pa0, pa1, pa2, pa3, b0, b1);
                mma_f16(o[2*np+1][0], o[2*np+1][1], o[2*np+1][2], o[2*np+1][3],
                        pa0, pa1, pa2, pa3, b2, b3);
            }
        }
        __syncthreads();
    }

    // ---- epilogue: normalize and store ----
    const float inv0 = 1.0f / l0;
    const float inv1 = 1.0f / l1;
    const int row0 = qb * 64 + w * 16 + g;
    float* ybase = y + (size_t)(b * TT) * CC + h * HD;
#pragma unroll
    for (int nt = 0; nt < 8; nt++) {
        int col = nt * 8 + tg * 2;
        float2 v0, v1;
        v0.x = o[nt][0] * inv0; v0.y = o[nt][1] * inv0;
        v1.x = o[nt][2] * inv1; v1.y = o[nt][3] * inv1;
        *(float2*)&ybase[(size_t)row0 * CC + col]       = v0;
        *(float2*)&ybase[(size_t)(row0 + 8) * CC + col] = v1;
    }
}

// ---------------------------------------------------------------------------
// Launch
// ---------------------------------------------------------------------------
extern "C" void kernel_launch(void* const* d_in, const int* in_sizes, int n_in,
                              void* d_out, int out_size)
{
    const float* x     = (const float*)d_in[0];   // [2,2048,1024]
    const float* w_qkv = (const float*)d_in[1];   // [1024,3072]
    const float* b_qkv = (const float*)d_in[2];   // [3072]
    const float* w_out = (const float*)d_in[3];   // [1024,1024]
    const float* b_out = (const float*)d_in[4];   // [1024]
    float* out = (float*)d_out;                   // [2,2048,1024]

    float *qkv, *yb;
    cudaGetSymbolAddress((void**)&qkv, g_qkv);
    cudaGetSymbolAddress((void**)&yb, g_y);

    // 1) QKV projection (tf32 tensor cores)
    gemm_tf32_bias<<<dim3(QKVN / 128, MROWS / 128), 256>>>(
        x, w_qkv, b_qkv, qkv, MROWS, QKVN, CC);

    // 2) Causal MHA via tensor cores -> y [4096,1024] (b,t,h,d)
    flash_attn_mma<<<dim3(TT / 64, BB * NH), 128>>>(qkv, yb);

    // 3) Output projection (tf32 tensor cores)
    gemm_tf32_bias<<<dim3(CC / 128, MROWS / 128), 256>>>(
        yb, w_out, b_out, out, MROWS, CC, CC);
}

// round 5
// speedup vs baseline: 5.8251x; 1.1111x over previous
#include <cuda_runtime.h>
#include <cuda_fp16.h>
#include <math.h>
#include <stdint.h>

// Problem constants
#define BB 2
#define TT 2048
#define CC 1024
#define NH 16
#define HD 64
#define MROWS (BB*TT)      // 4096
#define QKVN  (3*CC)       // 3072

// Scratch (allocation-free rule: __device__ globals)
__device__ float g_qkv[MROWS * QKVN];   // [4096, 3072]
__device__ float g_y[MROWS * CC];       // [4096, 1024]

// ---------------------------------------------------------------------------
// MMA / ldmatrix helpers
// ---------------------------------------------------------------------------
__device__ __forceinline__ uint32_t f2tf32(float f) {
    uint32_t u;
    asm("cvt.rna.tf32.f32 %0, %1;" : "=r"(u) : "f"(f));
    return u;
}

__device__ __forceinline__ void mma_tf32(
    float& c0, float& c1, float& c2, float& c3,
    uint32_t a0, uint32_t a1, uint32_t a2, uint32_t a3,
    uint32_t b0, uint32_t b1)
{
    asm volatile(
        "mma.sync.aligned.m16n8k8.row.col.f32.tf32.tf32.f32 "
        "{%0,%1,%2,%3}, {%4,%5,%6,%7}, {%8,%9}, {%0,%1,%2,%3};"
        : "+f"(c0), "+f"(c1), "+f"(c2), "+f"(c3)
        : "r"(a0), "r"(a1), "r"(a2), "r"(a3), "r"(b0), "r"(b1));
}

__device__ __forceinline__ void mma_f16(
    float& c0, float& c1, float& c2, float& c3,
    uint32_t a0, uint32_t a1, uint32_t a2, uint32_t a3,
    uint32_t b0, uint32_t b1)
{
    asm volatile(
        "mma.sync.aligned.m16n8k16.row.col.f32.f16.f16.f32 "
        "{%0,%1,%2,%3}, {%4,%5,%6,%7}, {%8,%9}, {%0,%1,%2,%3};"
        : "+f"(c0), "+f"(c1), "+f"(c2), "+f"(c3)
        : "r"(a0), "r"(a1), "r"(a2), "r"(a3), "r"(b0), "r"(b1));
}

__device__ __forceinline__ void ldsm_x4(
    uint32_t& r0, uint32_t& r1, uint32_t& r2, uint32_t& r3, uint32_t addr)
{
    asm volatile(
        "ldmatrix.sync.aligned.m8n8.x4.shared.b16 {%0,%1,%2,%3}, [%4];"
        : "=r"(r0), "=r"(r1), "=r"(r2), "=r"(r3) : "r"(addr));
}

__device__ __forceinline__ void ldsm_x4_trans(
    uint32_t& r0, uint32_t& r1, uint32_t& r2, uint32_t& r3, uint32_t addr)
{
    asm volatile(
        "ldmatrix.sync.aligned.m8n8.x4.trans.shared.b16 {%0,%1,%2,%3}, [%4];"
        : "=r"(r0), "=r"(r1), "=r"(r2), "=r"(r3) : "r"(addr));
}

// ---------------------------------------------------------------------------
// fp16 tensor-core GEMM with bias: out[M,N] = A[M,K] @ W[K,N] + bias[N]
// fp32 in/out; operands staged in smem as fp16 (same mantissa as tf32),
// f32 accumulate. BM=BN=128, BK=32, double-buffered smem, ldmatrix frags.
// 256 threads = 8 warps in 2(m) x 4(n), warp tile 64x32 (4x4 m16n8k16).
// ---------------------------------------------------------------------------
#define A_STRIDE 40    // halfs per As row (80B: 16B-aligned, ldsm conflict-free)
#define B_STRIDE 136   // halfs per Bs row (272B: 16B-aligned, ldsm conflict-free)

__global__ void __launch_bounds__(256) gemm_f16_bias(
    const float* __restrict__ A, const float* __restrict__ W,
    const float* __restrict__ bias, float* __restrict__ out,
    int M, int N, int K)
{
    constexpr int BK = 32;
    __shared__ __align__(16) __half As[2][128][A_STRIDE];
    __shared__ __align__(16) __half Bs[2][32][B_STRIDE];

    const int tid  = threadIdx.x;
    const int warp = tid >> 5;
    const int lane = tid & 31;
    const int g    = lane >> 2;
    const int tg   = lane & 3;

    const int wm = (warp & 1) * 64;
    const int wn = (warp >> 1) * 32;
    const int m0 = blockIdx.y * 128;
    const int n0 = blockIdx.x * 128;

    float acc[4][4][4];
#pragma unroll
    for (int i = 0; i < 4; i++)
#pragma unroll
        for (int j = 0; j < 4; j++)
#pragma unroll
            for (int r = 0; r < 4; r++) acc[i][j][r] = 0.0f;

    // staging mapping: A row per thread-pair, B row per 8 threads
    const int arow = tid >> 1, acol = (tid & 1) * 16;
    const int brow = tid >> 3, bcol = (tid & 7) * 16;

    const int niter = K / BK;

    float4 a4[4], b4[4];
#pragma unroll
    for (int i = 0; i < 4; i++) {
        a4[i] = *(const float4*)&A[(size_t)(m0 + arow) * K + acol + i * 4];
        b4[i] = *(const float4*)&W[(size_t)brow * N + n0 + bcol + i * 4];
    }
    // cvt + store tile 0
    {
        half2 ha[8], hb[8];
#pragma unroll
        for (int i = 0; i < 4; i++) {
            ha[2*i]   = __floats2half2_rn(a4[i].x, a4[i].y);
            ha[2*i+1] = __floats2half2_rn(a4[i].z, a4[i].w);
            hb[2*i]   = __floats2half2_rn(b4[i].x, b4[i].y);
            hb[2*i+1] = __floats2half2_rn(b4[i].z, b4[i].w);
        }
        *(uint4*)&As[0][arow][acol]     = *(uint4*)&ha[0];
        *(uint4*)&As[0][arow][acol + 8] = *(uint4*)&ha[4];
        *(uint4*)&Bs[0][brow][bcol]     = *(uint4*)&hb[0];
        *(uint4*)&Bs[0][brow][bcol + 8] = *(uint4*)&hb[4];
    }
    __syncthreads();

    for (int it = 0; it < niter; it++) {
        const int cur = it & 1;

        // 1) issue global prefetch for next tile
        if (it + 1 < niter) {
            int k0 = (it + 1) * BK;
#pragma unroll
            for (int i = 0; i < 4; i++) {
                a4[i] = *(const float4*)&A[(size_t)(m0 + arow) * K + k0 + acol + i * 4];
                b4[i] = *(const float4*)&W[(size_t)(k0 + brow) * N + n0 + bcol + i * 4];
            }
        }

        // 2) compute on current buffer (covers load latency)
#pragma unroll
        for (int kk = 0; kk < BK; kk += 16) {
            uint32_t af[4][4];
#pragma unroll
            for (int mt = 0; mt < 4; mt++) {
                uint32_t addr = (uint32_t)__cvta_generic_to_shared(
                    &As[cur][wm + mt * 16 + (lane & 15)][kk + (lane >> 4) * 8]);
                ldsm_x4(af[mt][0], af[mt][1], af[mt][2], af[mt][3], addr);
            }
            uint32_t bf[4][2];
#pragma unroll
            for (int nt2 = 0; nt2 < 2; nt2++) {
                uint32_t addr = (uint32_t)__cvta_generic_to_shared(
                    &Bs[cur][kk + (lane & 15)][wn + nt2 * 16 + (lane >> 4) * 8]);
                uint32_t r0, r1, r2, r3;
                ldsm_x4_trans(r0, r1, r2, r3, addr);
                bf[nt2 * 2][0] = r0; bf[nt2 * 2][1] = r1;
                bf[nt2 * 2 + 1][0] = r2; bf[nt2 * 2 + 1][1] = r3;
            }
#pragma unroll
            for (int mt = 0; mt < 4; mt++)
#pragma unroll
                for (int nt = 0; nt < 4; nt++)
                    mma_f16(acc[mt][nt][0], acc[mt][nt][1],
                            acc[mt][nt][2], acc[mt][nt][3],
                            af[mt][0], af[mt][1], af[mt][2], af[mt][3],
                            bf[nt][0], bf[nt][1]);
        }

        // 3) cvt + store next tile into the other buffer
        if (it + 1 < niter) {
            half2 ha[8], hb[8];
#pragma unroll
            for (int i = 0; i < 4; i++) {
                ha[2*i]   = __floats2half2_rn(a4[i].x, a4[i].y);
                ha[2*i+1] = __floats2half2_rn(a4[i].z, a4[i].w);
                hb[2*i]   = __floats2half2_rn(b4[i].x, b4[i].y);
                hb[2*i+1] = __floats2half2_rn(b4[i].z, b4[i].w);
            }
            *(uint4*)&As[1 - cur][arow][acol]     = *(uint4*)&ha[0];
            *(uint4*)&As[1 - cur][arow][acol + 8] = *(uint4*)&ha[4];
            *(uint4*)&Bs[1 - cur][brow][bcol]     = *(uint4*)&hb[0];
            *(uint4*)&Bs[1 - cur][brow][bcol + 8] = *(uint4*)&hb[4];
        }
        __syncthreads();
    }

    // Epilogue (m16n8 acc layout)
#pragma unroll
    for (int mt = 0; mt < 4; mt++) {
        int row = m0 + wm + mt * 16 + g;
#pragma unroll
        for (int nt = 0; nt < 4; nt++) {
            int col = n0 + wn + nt * 8 + tg * 2;
            float2 bv = *(const float2*)&bias[col];
            float2 v0, v1;
            v0.x = acc[mt][nt][0] + bv.x;
            v0.y = acc[mt][nt][1] + bv.y;
            v1.x = acc[mt][nt][2] + bv.x;
            v1.y = acc[mt][nt][3] + bv.y;
            *(float2*)&out[(size_t)row * N + col]       = v0;
            *(float2*)&out[(size_t)(row + 8) * N + col] = v1;
        }
    }
}

// ---------------------------------------------------------------------------
// Tensor-core causal flash attention (unchanged from R3).
// ---------------------------------------------------------------------------
#define KPAD 4
#define VPAD 8

__global__ void __launch_bounds__(128) flash_attn_mma(
    const float* __restrict__ qkv, float* __restrict__ y)
{
    const int qb  = blockIdx.x;
    const int bh  = blockIdx.y;
    const int b   = bh >> 4;
    const int h   = bh & 15;
    const int tid = threadIdx.x;
    const int w   = tid >> 5;
    const int lane = tid & 31;
    const int g   = lane >> 2;
    const int tg  = lane & 3;

    __shared__ __align__(16) float Ks[64][HD + KPAD];
    __shared__ __align__(16) __half Vs[64][HD + VPAD];

    const float* base = qkv + (size_t)(b * TT) * QKVN + h * HD;

    {
        for (int p = tid; p < 64 * 16; p += 128) {
            int r = p >> 4, c4 = p & 15;
            *(float4*)&Ks[r][c4 * 4] =
                *(const float4*)&base[(size_t)(qb * 64 + r) * QKVN + c4 * 4];
        }
        __syncthreads();
    }

    uint32_t aq[8][4];
    const float qscale = 0.125f;
#pragma unroll
    for (int kc = 0; kc < 8; kc++) {
        int r0 = w * 16 + g;
        aq[kc][0] = f2tf32(Ks[r0    ][kc * 8 + tg    ] * qscale);
        aq[kc][1] = f2tf32(Ks[r0 + 8][kc * 8 + tg    ] * qscale);
        aq[kc][2] = f2tf32(Ks[r0    ][kc * 8 + tg + 4] * qscale);
        aq[kc][3] = f2tf32(Ks[r0 + 8][kc * 8 + tg + 4] * qscale);
    }
    __syncthreads();

    float o[8][4];
#pragma unroll
    for (int nt = 0; nt < 8; nt++)
#pragma unroll
        for (int r = 0; r < 4; r++) o[nt][r] = 0.0f;
    float m0r = -INFINITY, m1r = -INFINITY;
    float l0 = 0.0f, l1 = 0.0f;

    const int ntiles = qb + 1;

    for (int t = 0; t < ntiles; t++) {
        const int kt = t * 64;
        const bool diag = (t == ntiles - 1);

        for (int p = tid; p < 64 * 16; p += 128) {
            int r = p >> 4, c4 = p & 15;
            const float* krow = base + (size_t)(kt + r) * QKVN + CC;
            *(float4*)&Ks[r][c4 * 4] = *(const float4*)&krow[c4 * 4];
            float4 v = *(const float4*)&krow[CC + c4 * 4];
            *(half2*)&Vs[r][c4 * 4]     = __floats2half2_rn(v.x, v.y);
            *(half2*)&Vs[r][c4 * 4 + 2] = __floats2half2_rn(v.z, v.w);
        }
        __syncthreads();

        float s[8][4];
#pragma unroll
        for (int nt = 0; nt < 8; nt++)
#pragma unroll
            for (int r = 0; r < 4; r++) s[nt][r] = 0.0f;

#pragma unroll
        for (int kc = 0; kc < 8; kc++) {
            uint32_t bf[8][2];
#pragma unroll
            for (int nt = 0; nt < 8; nt++) {
                bf[nt][0] = f2tf32(Ks[nt * 8 + g][kc * 8 + tg    ]);
                bf[nt][1] = f2tf32(Ks[nt * 8 + g][kc * 8 + tg + 4]);
            }
#pragma unroll
            for (int nt = 0; nt < 8; nt++)
                mma_tf32(s[nt][0], s[nt][1], s[nt][2], s[nt][3],
                         aq[kc][0], aq[kc][1], aq[kc][2], aq[kc][3],
                         bf[nt][0], bf[nt][1]);
        }

        if (diag) {
            int row0 = w * 16 + g;
            int row1 = row0 + 8;
#pragma unroll
            for (int nt = 0; nt < 8; nt++) {
                int c0 = nt * 8 + tg * 2;
                if (c0     > row0) s[nt][0] = -INFINITY;
                if (c0 + 1 > row0) s[nt][1] = -INFINITY;
                if (c0     > row1) s[nt][2] = -INFINITY;
                if (c0 + 1 > row1) s[nt][3] = -INFINITY;
            }
        }

        float cm0 = -INFINITY, cm1 = -INFINITY;
#pragma unroll
        for (int nt = 0; nt < 8; nt++) {
            cm0 = fmaxf(cm0, fmaxf(s[nt][0], s[nt][1]));
            cm1 = fmaxf(cm1, fmaxf(s[nt][2], s[nt][3]));
        }
        cm0 = fmaxf(cm0, __shfl_xor_sync(0xffffffffu, cm0, 1));
        cm0 = fmaxf(cm0, __shfl_xor_sync(0xffffffffu, cm0, 2));
        cm1 = fmaxf(cm1, __shfl_xor_sync(0xffffffffu, cm1, 1));
        cm1 = fmaxf(cm1, __shfl_xor_sync(0xffffffffu, cm1, 2));

        float mn0 = fmaxf(m0r, cm0);
        float mn1 = fmaxf(m1r, cm1);
        float corr0 = __expf(m0r - mn0);
        float corr1 = __expf(m1r - mn1);
        m0r = mn0; m1r = mn1;

        uint32_t p01[8], p23[8];
        float ps0 = 0.0f, ps1 = 0.0f;
#pragma unroll
        for (int nt = 0; nt < 8; nt++) {
            float e0 = __expf(s[nt][0] - mn0);
            float e1 = __expf(s[nt][1] - mn0);
            float e2 = __expf(s[nt][2] - mn1);
            float e3 = __expf(s[nt][3] - mn1);
            ps0 += e0 + e1;
            ps1 += e2 + e3;
            half2 h01 = __floats2half2_rn(e0, e1);
            half2 h23 = __floats2half2_rn(e2, e3);
            p01[nt] = *(uint32_t*)&h01;
            p23[nt] = *(uint32_t*)&h23;
        }
        ps0 += __shfl_xor_sync(0xffffffffu, ps0, 1);
        ps0 += __shfl_xor_sync(0xffffffffu, ps0, 2);
        ps1 += __shfl_xor_sync(0xffffffffu, ps1, 1);
        ps1 += __shfl_xor_sync(0xffffffffu, ps1, 2);
        l0 = l0 * corr0 + ps0;
        l1 = l1 * corr1 + ps1;

#pragma unroll
        for (int nt = 0; nt < 8; nt++) {
            o[nt][0] *= corr0; o[nt][1] *= corr0;
            o[nt][2] *= corr1; o[nt][3] *= corr1;
        }

#pragma unroll
        for (int kc = 0; kc < 4; kc++) {
            uint32_t pa0 = p01[2 * kc],     pa1 = p23[2 * kc];
            uint32_t pa2 = p01[2 * kc + 1], pa3 = p23[2 * kc + 1];
#pragma unroll
            for (int np = 0; np < 4; np++) {
                int sub = lane >> 3;
                int key = kc * 16 + (lane & 7) + (sub & 1) * 8;
                int dim = np * 16 + (sub >> 1) * 8;
                uint32_t addr = (uint32_t)__cvta_generic_to_shared(&Vs[key][dim]);
                uint32_t b0, b1, b2, b3;
                ldsm_x4_trans(b0, b1, b2, b3, addr);
                mma_f16(o[2*np][0], o[2*np][1], o[2*np][2], o[2*np][3],
                        pa0, pa1, pa2, pa3, b0, b1);
                mma_f16(o[2*np+1][0], o[2*np+1][1], o[2*np+1][2], o[2*np+1][3],
                        pa0, pa1, pa2, pa3, b2, b3);
            }
        }
        __syncthreads();
    }

    const float inv0 = 1.0f / l0;
    const float inv1 = 1.0f / l1;
    const int row0 = qb * 64 + w * 16 + g;
    float* ybase = y + (size_t)(b * TT) * CC + h * HD;
#pragma unroll
    for (int nt = 0; nt < 8; nt++) {
        int col = nt * 8 + tg * 2;
        float2 v0, v1;
        v0.x = o[nt][0] * inv0; v0.y = o[nt][1] * inv0;
        v1.x = o[nt][2] * inv1; v1.y = o[nt][3] * inv1;
        *(float2*)&ybase[(size_t)row0 * CC + col]       = v0;
        *(float2*)&ybase[(size_t)(row0 + 8) * CC + col] = v1;
    }
}

// ---------------------------------------------------------------------------
// Launch
// ---------------------------------------------------------------------------
extern "C" void kernel_launch(void* const* d_in, const int* in_sizes, int n_in,
                              void* d_out, int out_size)
{
    const float* x     = (const float*)d_in[0];
    const float* w_qkv = (const float*)d_in[1];
    const float* b_qkv = (const float*)d_in[2];
    const float* w_out = (const float*)d_in[3];
    const float* b_out = (const float*)d_in[4];
    float* out = (float*)d_out;

    float *qkv, *yb;
    cudaGetSymbolAddress((void**)&qkv, g_qkv);
    cudaGetSymbolAddress((void**)&yb, g_y);

    // 1) QKV projection (fp16 tensor cores, f32 accumulate)
    gemm_f16_bias<<<dim3(QKVN / 128, MROWS / 128), 256>>>(
        x, w_qkv, b_qkv, qkv, MROWS, QKVN, CC);

    // 2) Causal MHA via tensor cores -> y [4096,1024] (b,t,h,d)
    flash_attn_mma<<<dim3(TT / 64, BB * NH), 128>>>(qkv, yb);

    // 3) Output projection (fp16 tensor cores)
    gemm_f16_bias<<<dim3(CC / 128, MROWS / 128), 256>>>(
        yb, w_out, b_out, out, MROWS, CC, CC);
}

// round 6
// speedup vs baseline: 7.9869x; 1.3711x over previous
#include <cuda_runtime.h>
#include <cuda_fp16.h>
#include <math.h>
#include <stdint.h>

// Problem constants
#define BB 2
#define TT 2048
#define CC 1024
#define NH 16
#define HD 64
#define MROWS (BB*TT)      // 4096
#define QKVN  (3*CC)       // 3072

// Scratch (allocation-free rule: __device__ globals)
__device__ __half g_xh[MROWS * CC];        // x in fp16
__device__ __half g_wqkvh[CC * QKVN];      // w_qkv in fp16
__device__ __half g_wouth[CC * CC];        // w_out in fp16
__device__ __half g_qkv[MROWS * QKVN];     // qkv activations fp16
__device__ __half g_y[MROWS * CC];         // attention output fp16

// ---------------------------------------------------------------------------
// helpers
// ---------------------------------------------------------------------------
__device__ __forceinline__ void mma_f16(
    float& c0, float& c1, float& c2, float& c3,
    uint32_t a0, uint32_t a1, uint32_t a2, uint32_t a3,
    uint32_t b0, uint32_t b1)
{
    asm volatile(
        "mma.sync.aligned.m16n8k16.row.col.f32.f16.f16.f32 "
        "{%0,%1,%2,%3}, {%4,%5,%6,%7}, {%8,%9}, {%0,%1,%2,%3};"
        : "+f"(c0), "+f"(c1), "+f"(c2), "+f"(c3)
        : "r"(a0), "r"(a1), "r"(a2), "r"(a3), "r"(b0), "r"(b1));
}

__device__ __forceinline__ void ldsm_x4(
    uint32_t& r0, uint32_t& r1, uint32_t& r2, uint32_t& r3, uint32_t addr)
{
    asm volatile(
        "ldmatrix.sync.aligned.m8n8.x4.shared.b16 {%0,%1,%2,%3}, [%4];"
        : "=r"(r0), "=r"(r1), "=r"(r2), "=r"(r3) : "r"(addr));
}

__device__ __forceinline__ void ldsm_x4_trans(
    uint32_t& r0, uint32_t& r1, uint32_t& r2, uint32_t& r3, uint32_t addr)
{
    asm volatile(
        "ldmatrix.sync.aligned.m8n8.x4.trans.shared.b16 {%0,%1,%2,%3}, [%4];"
        : "=r"(r0), "=r"(r1), "=r"(r2), "=r"(r3) : "r"(addr));
}

__device__ __forceinline__ void cp_async16(uint32_t smem, const void* gmem) {
    asm volatile("cp.async.cg.shared.global [%0], [%1], 16;"
                 :: "r"(smem), "l"(gmem));
}
__device__ __forceinline__ void cp_commit() {
    asm volatile("cp.async.commit_group;");
}
template<int N>
__device__ __forceinline__ void cp_wait() {
    asm volatile("cp.async.wait_group %0;" :: "n"(N));
}

// ---------------------------------------------------------------------------
// fp32 -> fp16 conversion (grid-stride over float4 pairs; n % 8 == 0)
// ---------------------------------------------------------------------------
__global__ void f32_to_f16_kernel(const float* __restrict__ in,
                                  __half* __restrict__ out, int n)
{
    int i = (blockIdx.x * blockDim.x + threadIdx.x) * 8;
    if (i < n) {
        float4 a = *(const float4*)&in[i];
        float4 b = *(const float4*)&in[i + 4];
        half2 h[4];
        h[0] = __floats2half2_rn(a.x, a.y);
        h[1] = __floats2half2_rn(a.z, a.w);
        h[2] = __floats2half2_rn(b.x, b.y);
        h[3] = __floats2half2_rn(b.z, b.w);
        *(uint4*)&out[i] = *(uint4*)&h[0];
    }
}

// ---------------------------------------------------------------------------
// fp16 tensor-core GEMM with bias, cp.async 3-stage pipeline.
// out[M,N] = A[M,K] @ W[K,N] + bias[N]; A,W fp16; out fp16 or fp32.
// BM=BN=128, BK=32, 256 threads = 8 warps (2m x 4n), warp tile 64x32.
// ---------------------------------------------------------------------------
#define ASTR 40    // halfs per As row (80B, 16B-aligned, ldsm conflict-free)
#define BSTR 136   // halfs per Bs row (272B)
#define STAGES 3

template<bool HALF_OUT>
__global__ void __launch_bounds__(256) gemm_f16_pipe(
    const __half* __restrict__ A, const __half* __restrict__ W,
    const float* __restrict__ bias, void* __restrict__ outp,
    int M, int N, int K)
{
    __shared__ __align__(16) __half As[STAGES][128][ASTR];
    __shared__ __align__(16) __half Bs[STAGES][32][BSTR];

    const int tid  = threadIdx.x;
    const int warp = tid >> 5;
    const int lane = tid & 31;
    const int g    = lane >> 2;
    const int tg   = lane & 3;

    const int wm = (warp & 1) * 64;
    const int wn = (warp >> 1) * 32;
    const int m0 = blockIdx.y * 128;
    const int n0 = blockIdx.x * 128;

    float acc[4][4][4];
#pragma unroll
    for (int i = 0; i < 4; i++)
#pragma unroll
        for (int j = 0; j < 4; j++)
#pragma unroll
            for (int r = 0; r < 4; r++) acc[i][j][r] = 0.0f;

    // cp.async mapping: 2 x 16B per thread per tensor
    const int arow = tid >> 1, acol = (tid & 1) * 16;
    const int brow = tid >> 3, bcol = (tid & 7) * 16;

    const int NI = K / 32;

    auto issue = [&](int stage, int k0) {
        uint32_t sa = (uint32_t)__cvta_generic_to_shared(&As[stage][arow][acol]);
        const __half* ga = &A[(size_t)(m0 + arow) * K + k0 + acol];
        cp_async16(sa,      ga);
        cp_async16(sa + 16, ga + 8);
        uint32_t sb = (uint32_t)__cvta_generic_to_shared(&Bs[stage][brow][bcol]);
        const __half* gb = &W[(size_t)(k0 + brow) * N + n0 + bcol];
        cp_async16(sb,      gb);
        cp_async16(sb + 16, gb + 8);
    };

    // Prologue: stages 0..STAGES-2
#pragma unroll
    for (int s = 0; s < STAGES - 1; s++) {
        if (s < NI) issue(s, s * 32);
        cp_commit();
    }

    for (int it = 0; it < NI; it++) {
        cp_wait<STAGES - 2>();     // stage it landed
        __syncthreads();           // all warps done with compute(it-1) on the slot we refill

        // refill the just-freed slot
        int nxt = it + STAGES - 1;
        if (nxt < NI) issue(nxt % STAGES, nxt * 32);
        cp_commit();

        const int cur = it % STAGES;
#pragma unroll
        for (int kk = 0; kk < 32; kk += 16) {
            uint32_t af[4][4];
#pragma unroll
            for (int mt = 0; mt < 4; mt++) {
                uint32_t addr = (uint32_t)__cvta_generic_to_shared(
                    &As[cur][wm + mt * 16 + (lane & 15)][kk + (lane >> 4) * 8]);
                ldsm_x4(af[mt][0], af[mt][1], af[mt][2], af[mt][3], addr);
            }
            uint32_t bf[4][2];
#pragma unroll
            for (int nt2 = 0; nt2 < 2; nt2++) {
                uint32_t addr = (uint32_t)__cvta_generic_to_shared(
                    &Bs[cur][kk + (lane & 15)][wn + nt2 * 16 + (lane >> 4) * 8]);
                uint32_t r0, r1, r2, r3;
                ldsm_x4_trans(r0, r1, r2, r3, addr);
                bf[nt2 * 2][0] = r0;     bf[nt2 * 2][1] = r1;
                bf[nt2 * 2 + 1][0] = r2; bf[nt2 * 2 + 1][1] = r3;
            }
#pragma unroll
            for (int mt = 0; mt < 4; mt++)
#pragma unroll
                for (int nt = 0; nt < 4; nt++)
                    mma_f16(acc[mt][nt][0], acc[mt][nt][1],
                            acc[mt][nt][2], acc[mt][nt][3],
                            af[mt][0], af[mt][1], af[mt][2], af[mt][3],
                            bf[nt][0], bf[nt][1]);
        }
    }

    // Epilogue
#pragma unroll
    for (int mt = 0; mt < 4; mt++) {
        int row = m0 + wm + mt * 16 + g;
#pragma unroll
        for (int nt = 0; nt < 4; nt++) {
            int col = n0 + wn + nt * 8 + tg * 2;
            float2 bv = *(const float2*)&bias[col];
            float v00 = acc[mt][nt][0] + bv.x;
            float v01 = acc[mt][nt][1] + bv.y;
            float v10 = acc[mt][nt][2] + bv.x;
            float v11 = acc[mt][nt][3] + bv.y;
            if (HALF_OUT) {
                __half* out = (__half*)outp;
                half2 h0 = __floats2half2_rn(v00, v01);
                half2 h1 = __floats2half2_rn(v10, v11);
                *(half2*)&out[(size_t)row * N + col]       = h0;
                *(half2*)&out[(size_t)(row + 8) * N + col] = h1;
            } else {
                float* out = (float*)outp;
                *(float2*)&out[(size_t)row * N + col]       = make_float2(v00, v01);
                *(float2*)&out[(size_t)(row + 8) * N + col] = make_float2(v10, v11);
            }
        }
    }
}

// ---------------------------------------------------------------------------
// All-fp16 tensor-core causal flash attention.
// Grid: (T/64, B*NH). Block: 128 threads = 4 warps; warp w owns query rows
// [w*16, w*16+16). S = Q K^T and O += P V both m16n8k16 fp16 HMMA.
// K rows [key][dim] are directly the n8k16 B-fragment via non-trans ldsm.
// Scale 1/sqrt(D) applied to S after MMA. Softmax f32. y written fp16.
// ---------------------------------------------------------------------------
#define QSTR 72    // halfs per smem row (144B)

__global__ void __launch_bounds__(128) flash_attn_f16(
    const __half* __restrict__ qkv, __half* __restrict__ y)
{
    const int qb  = blockIdx.x;            // 0..31
    const int bh  = blockIdx.y;            // 0..31
    const int b   = bh >> 4;
    const int h   = bh & 15;
    const int tid = threadIdx.x;
    const int w   = tid >> 5;
    const int lane = tid & 31;
    const int g   = lane >> 2;
    const int tg  = lane & 3;

    __shared__ __align__(16) __half Qs[64][QSTR];
    __shared__ __align__(16) __half Ks[64][QSTR];
    __shared__ __align__(16) __half Vs[64][QSTR];

    const __half* base = qkv + (size_t)(b * TT) * QKVN + h * HD;

    // ---- load Q tile (64 x 64 halfs) ----
    for (int p = tid; p < 64 * 8; p += 128) {
        int r = p >> 3, c = p & 7;
        *(uint4*)&Qs[r][c * 8] =
            *(const uint4*)&base[(size_t)(qb * 64 + r) * QKVN + c * 8];
    }
    __syncthreads();

    // ---- Q A-fragments: 4 k16-chunks ----
    uint32_t aq[4][4];
#pragma unroll
    for (int kc = 0; kc < 4; kc++) {
        uint32_t addr = (uint32_t)__cvta_generic_to_shared(
            &Qs[w * 16 + (lane & 15)][kc * 16 + (lane >> 4) * 8]);
        ldsm_x4(aq[kc][0], aq[kc][1], aq[kc][2], aq[kc][3], addr);
    }

    float o[8][4];
#pragma unroll
    for (int nt = 0; nt < 8; nt++)
#pragma unroll
        for (int r = 0; r < 4; r++) o[nt][r] = 0.0f;
    float m0r = -INFINITY, m1r = -INFINITY;
    float l0 = 0.0f, l1 = 0.0f;
    const float scale = 0.125f;

    const int ntiles = qb + 1;

    for (int t = 0; t < ntiles; t++) {
        const int kt = t * 64;
        const bool diag = (t == ntiles - 1);

        // ---- load K,V tiles (fp16 straight copy) ----
        for (int p = tid; p < 64 * 8; p += 128) {
            int r = p >> 3, c = p & 7;
            const __half* krow = base + (size_t)(kt + r) * QKVN + CC;
            *(uint4*)&Ks[r][c * 8] = *(const uint4*)&krow[c * 8];
            *(uint4*)&Vs[r][c * 8] = *(const uint4*)&krow[CC + c * 8];
        }
        __syncthreads();

        // ---- S = Q K^T ----
        float s[8][4];
#pragma unroll
        for (int nt = 0; nt < 8; nt++)
#pragma unroll
            for (int r = 0; r < 4; r++) s[nt][r] = 0.0f;

#pragma unroll
        for (int kc = 0; kc < 4; kc++) {
            uint32_t bf[8][2];
#pragma unroll
            for (int nt2 = 0; nt2 < 4; nt2++) {
                uint32_t addr = (uint32_t)__cvta_generic_to_shared(
                    &Ks[nt2 * 16 + (lane & 7) + ((lane >> 4) & 1) * 8]
                       [kc * 16 + ((lane >> 3) & 1) * 8]);
                uint32_t r0, r1, r2, r3;
                ldsm_x4(r0, r1, r2, r3, addr);
                bf[nt2 * 2][0] = r0;     bf[nt2 * 2][1] = r1;
                bf[nt2 * 2 + 1][0] = r2; bf[nt2 * 2 + 1][1] = r3;
            }
#pragma unroll
            for (int nt = 0; nt < 8; nt++)
                mma_f16(s[nt][0], s[nt][1], s[nt][2], s[nt][3],
                        aq[kc][0], aq[kc][1], aq[kc][2], aq[kc][3],
                        bf[nt][0], bf[nt][1]);
        }

        // ---- scale + causal mask ----
#pragma unroll
        for (int nt = 0; nt < 8; nt++)
#pragma unroll
            for (int r = 0; r < 4; r++) s[nt][r] *= scale;

        if (diag) {
            int row0 = w * 16 + g;
            int row1 = row0 + 8;
#pragma unroll
            for (int nt = 0; nt < 8; nt++) {
                int c0 = nt * 8 + tg * 2;
                if (c0     > row0) s[nt][0] = -INFINITY;
                if (c0 + 1 > row0) s[nt][1] = -INFINITY;
                if (c0     > row1) s[nt][2] = -INFINITY;
                if (c0 + 1 > row1) s[nt][3] = -INFINITY;
            }
        }

        // ---- row max (across tg-quad: lanes xor 1, 2) ----
        float cm0 = -INFINITY, cm1 = -INFINITY;
#pragma unroll
        for (int nt = 0; nt < 8; nt++) {
            cm0 = fmaxf(cm0, fmaxf(s[nt][0], s[nt][1]));
            cm1 = fmaxf(cm1, fmaxf(s[nt][2], s[nt][3]));
        }
        cm0 = fmaxf(cm0, __shfl_xor_sync(0xffffffffu, cm0, 1));
        cm0 = fmaxf(cm0, __shfl_xor_sync(0xffffffffu, cm0, 2));
        cm1 = fmaxf(cm1, __shfl_xor_sync(0xffffffffu, cm1, 1));
        cm1 = fmaxf(cm1, __shfl_xor_sync(0xffffffffu, cm1, 2));

        float mn0 = fmaxf(m0r, cm0);
        float mn1 = fmaxf(m1r, cm1);
        float corr0 = __expf(m0r - mn0);
        float corr1 = __expf(m1r - mn1);
        m0r = mn0; m1r = mn1;

        // ---- P = exp(S - m) ----
        uint32_t p01[8], p23[8];
        float ps0 = 0.0f, ps1 = 0.0f;
#pragma unroll
        for (int nt = 0; nt < 8; nt++) {
            float e0 = __expf(s[nt][0] - mn0);
            float e1 = __expf(s[nt][1] - mn0);
            float e2 = __expf(s[nt][2] - mn1);
            float e3 = __expf(s[nt][3] - mn1);
            ps0 += e0 + e1;
            ps1 += e2 + e3;
            half2 h01 = __floats2half2_rn(e0, e1);
            half2 h23 = __floats2half2_rn(e2, e3);
            p01[nt] = *(uint32_t*)&h01;
            p23[nt] = *(uint32_t*)&h23;
        }
        ps0 += __shfl_xor_sync(0xffffffffu, ps0, 1);
        ps0 += __shfl_xor_sync(0xffffffffu, ps0, 2);
        ps1 += __shfl_xor_sync(0xffffffffu, ps1, 1);
        ps1 += __shfl_xor_sync(0xffffffffu, ps1, 2);
        l0 = l0 * corr0 + ps0;
        l1 = l1 * corr1 + ps1;

#pragma unroll
        for (int nt = 0; nt < 8; nt++) {
            o[nt][0] *= corr0; o[nt][1] *= corr0;
            o[nt][2] *= corr1; o[nt][3] *= corr1;
        }

        // ---- O += P V ----
#pragma unroll
        for (int kc = 0; kc < 4; kc++) {
            uint32_t pa0 = p01[2 * kc],     pa1 = p23[2 * kc];
            uint32_t pa2 = p01[2 * kc + 1], pa3 = p23[2 * kc + 1];
#pragma unroll
            for (int np = 0; np < 4; np++) {
                int sub = lane >> 3;
                int key = kc * 16 + (lane & 7) + (sub & 1) * 8;
                int dim = np * 16 + (sub >> 1) * 8;
                uint32_t addr = (uint32_t)__cvta_generic_to_shared(&Vs[key][dim]);
                uint32_t b0, b1, b2, b3;
                ldsm_x4_trans(b0, b1, b2, b3, addr);
                mma_f16(o[2*np][0], o[2*np][1], o[2*np][2], o[2*np][3],
                        pa0, pa1, pa2, pa3, b0, b1);
                mma_f16(o[2*np+1][0], o[2*np+1][1], o[2*np+1][2], o[2*np+1][3],
                        pa0, pa1, pa2, pa3, b2, b3);
            }
        }
        __syncthreads();
    }

    // ---- epilogue: normalize, store fp16 y ----
    const float inv0 = 1.0f / l0;
    const float inv1 = 1.0f / l1;
    const int row0 = qb * 64 + w * 16 + g;
    __half* ybase = y + (size_t)(b * TT) * CC + h * HD;
#pragma unroll
    for (int nt = 0; nt < 8; nt++) {
        int col = nt * 8 + tg * 2;
        half2 h0 = __floats2half2_rn(o[nt][0] * inv0, o[nt][1] * inv0);
        half2 h1 = __floats2half2_rn(o[nt][2] * inv1, o[nt][3] * inv1);
        *(half2*)&ybase[(size_t)row0 * CC + col]       = h0;
        *(half2*)&ybase[(size_t)(row0 + 8) * CC + col] = h1;
    }
}

// ---------------------------------------------------------------------------
// Launch
// ---------------------------------------------------------------------------
extern "C" void kernel_launch(void* const* d_in, const int* in_sizes, int n_in,
                              void* d_out, int out_size)
{
    const float* x     = (const float*)d_in[0];
    const float* w_qkv = (const float*)d_in[1];
    const float* b_qkv = (const float*)d_in[2];
    const float* w_out = (const float*)d_in[3];
    const float* b_out = (const float*)d_in[4];
    float* out = (float*)d_out;

    __half *xh, *wqkvh, *wouth, *qkv, *yb;
    cudaGetSymbolAddress((void**)&xh, g_xh);
    cudaGetSymbolAddress((void**)&wqkvh, g_wqkvh);
    cudaGetSymbolAddress((void**)&wouth, g_wouth);
    cudaGetSymbolAddress((void**)&qkv, g_qkv);
    cudaGetSymbolAddress((void**)&yb, g_y);

    // 0) fp32 -> fp16 conversions
    f32_to_f16_kernel<<<(MROWS * CC / 8 + 255) / 256, 256>>>(x, xh, MROWS * CC);
    f32_to_f16_kernel<<<(CC * QKVN / 8 + 255) / 256, 256>>>(w_qkv, wqkvh, CC * QKVN);
    f32_to_f16_kernel<<<(CC * CC / 8 + 255) / 256, 256>>>(w_out, wouth, CC * CC);

    // 1) QKV projection -> fp16 qkv
    gemm_f16_pipe<true><<<dim3(QKVN / 128, MROWS / 128), 256>>>(
        xh, wqkvh, b_qkv, qkv, MROWS, QKVN, CC);

    // 2) Causal MHA (all fp16 MMA) -> fp16 y
    flash_attn_f16<<<dim3(TT / 64, BB * NH), 128>>>(qkv, yb);

    // 3) Output projection -> fp32 out
    gemm_f16_pipe<false><<<dim3(CC / 128, MROWS / 128), 256>>>(
        yb, wouth, b_out, out, MROWS, CC, CC);
}